// round 1
// baseline (speedup 1.0000x reference)
#include <cuda_runtime.h>
#include <math.h>

// Problem constants
#define Bn  4
#define Sn  2048
#define Dn  1024
#define DKn 128

// ---------------- device scratch (no allocations allowed) ----------------
__device__ float g_Q[(size_t)Bn * Sn * DKn];            // 4 MB
__device__ float g_K[(size_t)Bn * Sn * DKn];            // 4 MB
__device__ float g_V[(size_t)Bn * Sn * Dn];             // 32 MB
__device__ float g_P[(size_t)Bn * Sn * Sn];             // 64 MB
__device__ unsigned char g_pad[Bn * Sn];
__device__ int g_fu[Bn];                                 // first unpadded index per batch

// ---------------- mask canonicalization ----------------
// padding_mask is a bool array host-side; the harness may marshal it as uint8
// or int32. Detect: padding is a contiguous NONEMPTY tail per row (index S-1 is
// always padded), so if the layout is uint8 there is a nonzero byte at an index
// not divisible by 4. If int32 (values 0/1 LE), bytes at i%4!=0 are all zero.
__global__ void mask_setup_kernel(const unsigned char* __restrict__ raw) {
    __shared__ int s_u8;
    __shared__ int s_fu[Bn];
    int t = threadIdx.x;
    if (t == 0) s_u8 = 0;
    if (t < Bn) s_fu[t] = Sn;
    __syncthreads();
    int local = 0;
    for (int i = t; i < Bn * Sn; i += blockDim.x)
        if ((i & 3) && raw[i]) local = 1;
    if (local) atomicOr(&s_u8, 1);
    __syncthreads();
    const bool u8 = (s_u8 != 0);
    const int* raw32 = (const int*)raw;
    for (int i = t; i < Bn * Sn; i += blockDim.x) {
        int pv = u8 ? (int)raw[i] : raw32[i];
        unsigned char p = (pv != 0) ? 1 : 0;
        g_pad[i] = p;
        if (!p) atomicMin(&s_fu[i / Sn], i % Sn);
    }
    __syncthreads();
    if (t < Bn) g_fu[t] = s_fu[t];
}

// ---------------- generic tiled fp32 GEMM: C = A[M,K] @ B[K,N] (+bias) -----
// 64x64 tile, depth chunk 16, 256 threads, 4x4 register blocking.
#define TM 64
#define TN 64
#define TK 16

__global__ __launch_bounds__(256)
void gemm_kernel(const float* __restrict__ A, const float* __restrict__ Bm,
                 const float* __restrict__ bias, float* __restrict__ C,
                 int M, int N, int K,
                 long strA, long strB, long strC) {
    __shared__ float As[TK][TM];
    __shared__ float Bs[TK][TN];
    const int t  = threadIdx.x;
    const int tx = t & 15, ty = t >> 4;
    const int row0 = blockIdx.y * TM;
    const int col0 = blockIdx.x * TN;
    const float* Ab = A  + (long)blockIdx.z * strA;
    const float* Bb = Bm + (long)blockIdx.z * strB;
    float*       Cb = C  + (long)blockIdx.z * strC;

    const int ar = t >> 2, ac = (t & 3) * 4;   // A tile: 64 rows x 16 depth
    const int bc = t >> 4, bn = (t & 15) * 4;  // B tile: 16 depth x 64 cols

    float acc[4][4] = {};
    for (int k0 = 0; k0 < K; k0 += TK) {
        float4 av = *(const float4*)&Ab[(long)(row0 + ar) * K + k0 + ac];
        float4 bv = *(const float4*)&Bb[(long)(k0 + bc) * N + col0 + bn];
        As[ac + 0][ar] = av.x; As[ac + 1][ar] = av.y;
        As[ac + 2][ar] = av.z; As[ac + 3][ar] = av.w;
        *(float4*)&Bs[bc][bn] = bv;
        __syncthreads();
#pragma unroll
        for (int kk = 0; kk < TK; kk++) {
            float4 a = *(const float4*)&As[kk][ty * 4];
            float4 b = *(const float4*)&Bs[kk][tx * 4];
            float ai[4] = {a.x, a.y, a.z, a.w};
            float bj[4] = {b.x, b.y, b.z, b.w};
#pragma unroll
            for (int i = 0; i < 4; i++)
#pragma unroll
                for (int j = 0; j < 4; j++)
                    acc[i][j] = fmaf(ai[i], bj[j], acc[i][j]);
        }
        __syncthreads();
    }
#pragma unroll
    for (int i = 0; i < 4; i++) {
        const int r = row0 + ty * 4 + i;
#pragma unroll
        for (int j = 0; j < 4; j++) {
            const int c = col0 + tx * 4 + j;
            float v = acc[i][j];
            if (bias) v += bias[c];
            Cb[(long)r * N + c] = v;
        }
    }
}

// ---------------- scores: S[b,q,k] = (Q[b,q] . K[b,k]) / sqrt(DK), masked ---
__global__ __launch_bounds__(256)
void scores_kernel(const float* __restrict__ Qg, const float* __restrict__ Kg,
                   float* __restrict__ P) {
    __shared__ float Qs[TK][TM];
    __shared__ float Ks[TK][TN];
    const int b = blockIdx.z;
    const int t = threadIdx.x;
    const int tx = t & 15, ty = t >> 4;
    const int q0 = blockIdx.y * TM;
    const int k0 = blockIdx.x * TN;
    const float* Qb = Qg + (long)b * Sn * DKn;
    const float* Kb = Kg + (long)b * Sn * DKn;

    const int ar = t >> 2, ac = (t & 3) * 4;
    float acc[4][4] = {};
    const bool any_live = (k0 <= q0 + TM - 1);   // tiles fully above diagonal skip MMA
    if (any_live) {
        for (int d0 = 0; d0 < DKn; d0 += TK) {
            float4 qv = *(const float4*)&Qb[(long)(q0 + ar) * DKn + d0 + ac];
            float4 kv = *(const float4*)&Kb[(long)(k0 + ar) * DKn + d0 + ac];
            Qs[ac + 0][ar] = qv.x; Qs[ac + 1][ar] = qv.y;
            Qs[ac + 2][ar] = qv.z; Qs[ac + 3][ar] = qv.w;
            Ks[ac + 0][ar] = kv.x; Ks[ac + 1][ar] = kv.y;
            Ks[ac + 2][ar] = kv.z; Ks[ac + 3][ar] = kv.w;
            __syncthreads();
#pragma unroll
            for (int kk = 0; kk < TK; kk++) {
                float4 a = *(const float4*)&Qs[kk][ty * 4];
                float4 c = *(const float4*)&Ks[kk][tx * 4];
                float ai[4] = {a.x, a.y, a.z, a.w};
                float bj[4] = {c.x, c.y, c.z, c.w};
#pragma unroll
                for (int i = 0; i < 4; i++)
#pragma unroll
                    for (int j = 0; j < 4; j++)
                        acc[i][j] = fmaf(ai[i], bj[j], acc[i][j]);
            }
            __syncthreads();
        }
    }
    const float inv_scale = 0.08838834764831845f;  // 1/sqrt(128)
    const int fu = g_fu[b];
    const unsigned char* pad = g_pad + b * Sn;
    float* Pb = P + (long)b * Sn * Sn;
#pragma unroll
    for (int i = 0; i < 4; i++) {
        const int q = q0 + ty * 4 + i;
        const bool uniform = (pad[q] != 0) || (fu > q);  // fully-masked row
#pragma unroll
        for (int j = 0; j < 4; j++) {
            const int k = k0 + tx * 4 + j;
            float v;
            if (uniform)                       v = 0.0f;
            else if (k <= q && pad[k] == 0)    v = acc[i][j] * inv_scale;
            else                               v = -INFINITY;
            Pb[(long)q * Sn + k] = v;
        }
    }
}

// ---------------- row softmax over S=2048, in place ----------------
__global__ __launch_bounds__(256)
void softmax_kernel(float* __restrict__ P) {
    const long row = blockIdx.x;
    float* p = P + row * (long)Sn;
    const int t = threadIdx.x;
    float4 v0 = ((float4*)p)[t];
    float4 v1 = ((float4*)p)[t + 256];

    float m = fmaxf(fmaxf(fmaxf(v0.x, v0.y), fmaxf(v0.z, v0.w)),
                    fmaxf(fmaxf(v1.x, v1.y), fmaxf(v1.z, v1.w)));
    __shared__ float red[8];
#pragma unroll
    for (int o = 16; o > 0; o >>= 1) m = fmaxf(m, __shfl_xor_sync(0xffffffff, m, o));
    if ((t & 31) == 0) red[t >> 5] = m;
    __syncthreads();
    if (t < 8) {
        float x = red[t];
#pragma unroll
        for (int o = 4; o > 0; o >>= 1) x = fmaxf(x, __shfl_xor_sync(0xff, x, o));
        red[t] = x;
    }
    __syncthreads();
    const float mx = red[0];
    __syncthreads();

    v0.x = expf(v0.x - mx); v0.y = expf(v0.y - mx);
    v0.z = expf(v0.z - mx); v0.w = expf(v0.w - mx);
    v1.x = expf(v1.x - mx); v1.y = expf(v1.y - mx);
    v1.z = expf(v1.z - mx); v1.w = expf(v1.w - mx);

    float s = (v0.x + v0.y + v0.z + v0.w) + (v1.x + v1.y + v1.z + v1.w);
#pragma unroll
    for (int o = 16; o > 0; o >>= 1) s += __shfl_xor_sync(0xffffffff, s, o);
    if ((t & 31) == 0) red[t >> 5] = s;
    __syncthreads();
    if (t < 8) {
        float x = red[t];
#pragma unroll
        for (int o = 4; o > 0; o >>= 1) x += __shfl_xor_sync(0xff, x, o);
        red[t] = x;
    }
    __syncthreads();
    const float inv = 1.0f / red[0];

    v0.x *= inv; v0.y *= inv; v0.z *= inv; v0.w *= inv;
    v1.x *= inv; v1.y *= inv; v1.z *= inv; v1.w *= inv;
    ((float4*)p)[t] = v0;
    ((float4*)p)[t + 256] = v1;
}

// ---------------- launch ----------------
extern "C" void kernel_launch(void* const* d_in, const int* in_sizes, int n_in,
                              void* d_out, int out_size) {
    const float* x  = (const float*)d_in[0];
    const unsigned char* pm = (const unsigned char*)d_in[1];
    const float* Wq = (const float*)d_in[2];
    const float* bq = (const float*)d_in[3];
    const float* Wk = (const float*)d_in[4];
    const float* bk = (const float*)d_in[5];
    const float* Wv = (const float*)d_in[6];
    const float* bv = (const float*)d_in[7];
    float* out = (float*)d_out;

    float *Qp, *Kp, *Vp, *Pp;
    cudaGetSymbolAddress((void**)&Qp, g_Q);
    cudaGetSymbolAddress((void**)&Kp, g_K);
    cudaGetSymbolAddress((void**)&Vp, g_V);
    cudaGetSymbolAddress((void**)&Pp, g_P);

    const int M = Bn * Sn;   // 8192
    dim3 blk(256);

    mask_setup_kernel<<<1, 256>>>(pm);
    // Q = x @ Wq + bq   [8192,128]
    gemm_kernel<<<dim3(DKn / TN, M / TM, 1), blk>>>(x, Wq, bq, Qp, M, DKn, Dn, 0, 0, 0);
    // K = x @ Wk + bk   [8192,128]
    gemm_kernel<<<dim3(DKn / TN, M / TM, 1), blk>>>(x, Wk, bk, Kp, M, DKn, Dn, 0, 0, 0);
    // V = x @ Wv + bv   [8192,1024]
    gemm_kernel<<<dim3(Dn / TN, M / TM, 1), blk>>>(x, Wv, bv, Vp, M, Dn, Dn, 0, 0, 0);
    // scores + mask -> P
    scores_kernel<<<dim3(Sn / TN, Sn / TM, Bn), blk>>>(Qp, Kp, Pp);
    // softmax rows
    softmax_kernel<<<Bn * Sn, 256>>>(Pp);
    // out[b] = P[b] @ V[b]
    gemm_kernel<<<dim3(Dn / TN, Sn / TM, Bn), blk>>>(
        Pp, Vp, nullptr, out, Sn, Dn, Sn,
        (long)Sn * Sn, (long)Sn * Dn, (long)Sn * Dn);
}

// round 2
// speedup vs baseline: 2.7619x; 2.7619x over previous
#include <cuda_runtime.h>
#include <math.h>

// Problem constants
#define Bn  4
#define Sn  2048
#define Dn  1024
#define DKn 128

// ---------------- device scratch (no allocations allowed) ----------------
__device__ float g_Q[(size_t)Bn * Sn * DKn];            // 4 MB
__device__ float g_K[(size_t)Bn * Sn * DKn];            // 4 MB
__device__ float g_V[(size_t)Bn * Sn * Dn];             // 32 MB
__device__ float g_P[(size_t)Bn * Sn * Sn];             // 64 MB
__device__ unsigned char g_pad[Bn * Sn];
__device__ int g_fu[Bn];                                 // first unpadded index per batch

// ---------------- mask canonicalization ----------------
__global__ void mask_setup_kernel(const unsigned char* __restrict__ raw) {
    __shared__ int s_u8;
    __shared__ int s_fu[Bn];
    int t = threadIdx.x;
    if (t == 0) s_u8 = 0;
    if (t < Bn) s_fu[t] = Sn;
    __syncthreads();
    int local = 0;
    for (int i = t; i < Bn * Sn; i += blockDim.x)
        if ((i & 3) && raw[i]) local = 1;
    if (local) atomicOr(&s_u8, 1);
    __syncthreads();
    const bool u8 = (s_u8 != 0);
    const int* raw32 = (const int*)raw;
    for (int i = t; i < Bn * Sn; i += blockDim.x) {
        int pv = u8 ? (int)raw[i] : raw32[i];
        unsigned char p = (pv != 0) ? 1 : 0;
        g_pad[i] = p;
        if (!p) atomicMin(&s_fu[i / Sn], i % Sn);
    }
    __syncthreads();
    if (t < Bn) g_fu[t] = s_fu[t];
}

// ---------------- tf32 helpers ----------------
__device__ __forceinline__ float to_tf32(float x) {
    unsigned u;
    asm("cvt.rna.tf32.f32 %0, %1;" : "=r"(u) : "f"(x));
    return __uint_as_float(u);
}

__device__ __forceinline__ void mma8(float* c,
                                     unsigned a0, unsigned a1, unsigned a2, unsigned a3,
                                     unsigned b0, unsigned b1) {
    asm volatile(
        "mma.sync.aligned.m16n8k8.row.col.f32.tf32.tf32.f32 "
        "{%0,%1,%2,%3}, {%4,%5,%6,%7}, {%8,%9}, {%0,%1,%2,%3};"
        : "+f"(c[0]), "+f"(c[1]), "+f"(c[2]), "+f"(c[3])
        : "r"(a0), "r"(a1), "r"(a2), "r"(a3), "r"(b0), "r"(b1));
}

// ---------------- tensor-core GEMM: C = A[M,K] @ B (+epilogue) ----------------
// 128x128 tile, k-chunk 16, 256 threads (8 warps, each 32x64).
// MODE: 0 = bias add (projection), 1 = scores (scale+mask), 2 = P@V (k-limit)
// BT:   0 = B row-major [K][N], 1 = B row-major [N][K] (use B^T)
#define BM 128
#define BN 128
#define BK 16
#define APAD 20
#define BPAD 136

template <int MODE, int BT>
__global__ __launch_bounds__(256)
void tc_gemm(const float* __restrict__ A, const float* __restrict__ B,
             const float* __restrict__ bias, float* __restrict__ C,
             int K, int lda, int ldb, int ldc,
             long strA, long strB, long strC) {
    __shared__ float As[2][BM][APAD];
    __shared__ float Bs[2][BK][BPAD];
    __shared__ unsigned char s_padq[BM], s_padk[BN];
    __shared__ int s_fu, s_uni;

    const int t  = threadIdx.x;
    const int z  = blockIdx.z;
    const int m0 = blockIdx.y * BM;
    const int n0 = blockIdx.x * BN;
    const float* Ab = A + (long)z * strA;
    const float* Bb = B + (long)z * strB;
    float*       Cb = C + (long)z * strC;

    int kEnd = K;
    if (MODE == 2) {
        if (t == 0) s_uni = 0;
        __syncthreads();
        if (t < BM) {
            int q = m0 + t;
            if (g_pad[z * Sn + q] || g_fu[z] > q) atomicOr(&s_uni, 1);
        }
        __syncthreads();
        kEnd = s_uni ? K : (m0 + BM);
    }
    int nChunks = kEnd / BK;
    if (MODE == 1) {
        if (n0 > m0 + BM - 1) nChunks = 0;          // tile fully above diagonal
        if (t < BM) s_padq[t] = g_pad[z * Sn + m0 + t];
        else        s_padk[t - BM] = g_pad[z * Sn + n0 + (t - BM)];
        if (t == 0) s_fu = g_fu[z];
        __syncthreads();
    }

    const int warp = t >> 5, lane = t & 31;
    const int g = lane >> 2, tig = lane & 3;
    const int wm = (warp & 3) * 32, wn = (warp >> 2) * 64;

    float acc[2][8][4] = {};

    // global-load / smem-store index precompute
    const int arow = t >> 1,  acg = (t & 1) * 8;   // A: 128 rows x 16
    const int brow = t >> 4,  bcg = (t & 15) * 8;  // B (row-major KxN): 16 x 128
    const int bnr  = t >> 1,  bkg = (t & 1) * 8;   // B^T (NxK): 128 rows x 16

    float aReg[8], bReg[8];

#define LOAD_GLOBAL(chunk) {                                                   \
    const float* ap = Ab + (long)(m0 + arow) * lda + (chunk) * BK + acg;       \
    float4 a0 = *(const float4*)ap; float4 a1 = *(const float4*)(ap + 4);      \
    aReg[0]=a0.x; aReg[1]=a0.y; aReg[2]=a0.z; aReg[3]=a0.w;                    \
    aReg[4]=a1.x; aReg[5]=a1.y; aReg[6]=a1.z; aReg[7]=a1.w;                    \
    if (!BT) {                                                                 \
        const float* bp = Bb + (long)((chunk) * BK + brow) * ldb + n0 + bcg;   \
        float4 b0 = *(const float4*)bp; float4 b1 = *(const float4*)(bp + 4);  \
        bReg[0]=b0.x; bReg[1]=b0.y; bReg[2]=b0.z; bReg[3]=b0.w;                \
        bReg[4]=b1.x; bReg[5]=b1.y; bReg[6]=b1.z; bReg[7]=b1.w;                \
    } else {                                                                   \
        const float* bp = Bb + (long)(n0 + bnr) * ldb + (chunk) * BK + bkg;    \
        float4 b0 = *(const float4*)bp; float4 b1 = *(const float4*)(bp + 4);  \
        bReg[0]=b0.x; bReg[1]=b0.y; bReg[2]=b0.z; bReg[3]=b0.w;                \
        bReg[4]=b1.x; bReg[5]=b1.y; bReg[6]=b1.z; bReg[7]=b1.w;                \
    } }

#define STORE_SMEM(buf) {                                                      \
    float* as = &As[buf][arow][acg];                                           \
    _Pragma("unroll") for (int j = 0; j < 8; j++) as[j] = to_tf32(aReg[j]);    \
    if (!BT) {                                                                 \
        float* bs = &Bs[buf][brow][bcg];                                       \
        _Pragma("unroll") for (int j = 0; j < 8; j++) bs[j] = to_tf32(bReg[j]);\
    } else {                                                                   \
        _Pragma("unroll") for (int j = 0; j < 8; j++)                          \
            Bs[buf][bkg + j][bnr] = to_tf32(bReg[j]);                          \
    } }

#define COMPUTE(buf) {                                                         \
    _Pragma("unroll") for (int ks = 0; ks < 2; ks++) {                         \
        unsigned af[2][4];                                                     \
        _Pragma("unroll") for (int mt = 0; mt < 2; mt++) {                     \
            int r = wm + mt * 16 + g;                                          \
            af[mt][0] = __float_as_uint(As[buf][r    ][ks * 8 + tig    ]);     \
            af[mt][1] = __float_as_uint(As[buf][r + 8][ks * 8 + tig    ]);     \
            af[mt][2] = __float_as_uint(As[buf][r    ][ks * 8 + tig + 4]);     \
            af[mt][3] = __float_as_uint(As[buf][r + 8][ks * 8 + tig + 4]);     \
        }                                                                      \
        unsigned bf[8][2];                                                     \
        _Pragma("unroll") for (int nt = 0; nt < 8; nt++) {                     \
            int cn = wn + nt * 8 + g;                                          \
            bf[nt][0] = __float_as_uint(Bs[buf][ks * 8 + tig    ][cn]);        \
            bf[nt][1] = __float_as_uint(Bs[buf][ks * 8 + tig + 4][cn]);        \
        }                                                                      \
        _Pragma("unroll") for (int mt = 0; mt < 2; mt++)                       \
            _Pragma("unroll") for (int nt = 0; nt < 8; nt++)                   \
                mma8(acc[mt][nt], af[mt][0], af[mt][1], af[mt][2], af[mt][3],  \
                     bf[nt][0], bf[nt][1]);                                    \
    } }

    if (nChunks > 0) {
        LOAD_GLOBAL(0);
        STORE_SMEM(0);
        __syncthreads();
        for (int i = 0; i < nChunks; i++) {
            const int cur = i & 1;
            if (i + 1 < nChunks) LOAD_GLOBAL(i + 1);
            COMPUTE(cur);
            if (i + 1 < nChunks) STORE_SMEM((i + 1) & 1);
            __syncthreads();
        }
    }

#undef LOAD_GLOBAL
#undef STORE_SMEM
#undef COMPUTE

    // ---------------- epilogue ----------------
    const float inv_scale = 0.08838834764831845f;  // 1/sqrt(128)
#pragma unroll
    for (int mt = 0; mt < 2; mt++) {
#pragma unroll
        for (int i = 0; i < 2; i++) {
            const int row  = wm + mt * 16 + g + i * 8;
            const int grow = m0 + row;
            bool uniform = false;
            if (MODE == 1) uniform = (s_padq[row] != 0) || (s_fu > grow);
#pragma unroll
            for (int nt = 0; nt < 8; nt++) {
                const int col = wn + nt * 8 + 2 * tig;
                float v0 = acc[mt][nt][i * 2 + 0];
                float v1 = acc[mt][nt][i * 2 + 1];
                if (MODE == 0) {
                    v0 += bias[n0 + col];
                    v1 += bias[n0 + col + 1];
                } else if (MODE == 1) {
                    const int kc = n0 + col;
                    if (uniform) { v0 = 0.0f; v1 = 0.0f; }
                    else {
                        v0 = (kc     <= grow && !s_padk[col])     ? v0 * inv_scale : -INFINITY;
                        v1 = (kc + 1 <= grow && !s_padk[col + 1]) ? v1 * inv_scale : -INFINITY;
                    }
                }
                *(float2*)&Cb[(long)grow * ldc + n0 + col] = make_float2(v0, v1);
            }
        }
    }
}

// ---------------- row softmax over S=2048, in place, causal-limited ----------
__global__ __launch_bounds__(256)
void softmax_kernel(float* __restrict__ P) {
    const int row = blockIdx.x;
    const int b = row >> 11, q = row & (Sn - 1);
    float* p = P + (long)row * Sn;
    const int t = threadIdx.x;

    const bool uniform = (g_pad[b * Sn + q] != 0) || (g_fu[b] > q);
    const int limit = uniform ? Sn : (q + 1);
    const int nvec = (limit + 3) >> 2;       // float4 count actually needed

    const float NEG = -INFINITY;
    const bool h0 = t < nvec, h1 = (t + 256) < nvec;
    float4 v0 = h0 ? ((float4*)p)[t]       : make_float4(NEG, NEG, NEG, NEG);
    float4 v1 = h1 ? ((float4*)p)[t + 256] : make_float4(NEG, NEG, NEG, NEG);

    float m = fmaxf(fmaxf(fmaxf(v0.x, v0.y), fmaxf(v0.z, v0.w)),
                    fmaxf(fmaxf(v1.x, v1.y), fmaxf(v1.z, v1.w)));
    __shared__ float red[8];
#pragma unroll
    for (int o = 16; o > 0; o >>= 1) m = fmaxf(m, __shfl_xor_sync(0xffffffff, m, o));
    if ((t & 31) == 0) red[t >> 5] = m;
    __syncthreads();
    if (t < 8) {
        float x = red[t];
#pragma unroll
        for (int o = 4; o > 0; o >>= 1) x = fmaxf(x, __shfl_xor_sync(0xff, x, o));
        red[t] = x;
    }
    __syncthreads();
    const float mx = red[0];
    __syncthreads();

    v0.x = __expf(v0.x - mx); v0.y = __expf(v0.y - mx);
    v0.z = __expf(v0.z - mx); v0.w = __expf(v0.w - mx);
    v1.x = __expf(v1.x - mx); v1.y = __expf(v1.y - mx);
    v1.z = __expf(v1.z - mx); v1.w = __expf(v1.w - mx);

    float s = (v0.x + v0.y + v0.z + v0.w) + (v1.x + v1.y + v1.z + v1.w);
#pragma unroll
    for (int o = 16; o > 0; o >>= 1) s += __shfl_xor_sync(0xffffffff, s, o);
    if ((t & 31) == 0) red[t >> 5] = s;
    __syncthreads();
    if (t < 8) {
        float x = red[t];
#pragma unroll
        for (int o = 4; o > 0; o >>= 1) x += __shfl_xor_sync(0xff, x, o);
        red[t] = x;
    }
    __syncthreads();
    const float inv = 1.0f / red[0];

    v0.x *= inv; v0.y *= inv; v0.z *= inv; v0.w *= inv;
    v1.x *= inv; v1.y *= inv; v1.z *= inv; v1.w *= inv;
    ((float4*)p)[t] = v0;          // beyond-limit lanes write exact zeros
    ((float4*)p)[t + 256] = v1;
}

// ---------------- launch ----------------
extern "C" void kernel_launch(void* const* d_in, const int* in_sizes, int n_in,
                              void* d_out, int out_size) {
    const float* x  = (const float*)d_in[0];
    const unsigned char* pm = (const unsigned char*)d_in[1];
    const float* Wq = (const float*)d_in[2];
    const float* bq = (const float*)d_in[3];
    const float* Wk = (const float*)d_in[4];
    const float* bk = (const float*)d_in[5];
    const float* Wv = (const float*)d_in[6];
    const float* bv = (const float*)d_in[7];
    float* out = (float*)d_out;

    float *Qp, *Kp, *Vp, *Pp;
    cudaGetSymbolAddress((void**)&Qp, g_Q);
    cudaGetSymbolAddress((void**)&Kp, g_K);
    cudaGetSymbolAddress((void**)&Vp, g_V);
    cudaGetSymbolAddress((void**)&Pp, g_P);

    const int M = Bn * Sn;   // 8192
    dim3 blk(256);

    mask_setup_kernel<<<1, 256>>>(pm);
    // Q = x @ Wq + bq : [8192,128]
    tc_gemm<0, 0><<<dim3(DKn / BN, M / BM, 1), blk>>>(
        x, Wq, bq, Qp, Dn, Dn, DKn, DKn, 0, 0, 0);
    // K = x @ Wk + bk : [8192,128]
    tc_gemm<0, 0><<<dim3(DKn / BN, M / BM, 1), blk>>>(
        x, Wk, bk, Kp, Dn, Dn, DKn, DKn, 0, 0, 0);
    // V = x @ Wv + bv : [8192,1024]
    tc_gemm<0, 0><<<dim3(Dn / BN, M / BM, 1), blk>>>(
        x, Wv, bv, Vp, Dn, Dn, Dn, Dn, 0, 0, 0);
    // scores: P[b,q,k] = (Q[b,q].K[b,k]) * inv_scale, masked  (B^T form)
    tc_gemm<1, 1><<<dim3(Sn / BN, Sn / BM, Bn), blk>>>(
        Qp, Kp, nullptr, Pp, DKn, DKn, DKn, Sn,
        (long)Sn * DKn, (long)Sn * DKn, (long)Sn * Sn);
    // softmax rows (causal-limited)
    softmax_kernel<<<Bn * Sn, 256>>>(Pp);
    // out[b] = P[b] @ V[b]  (k-limit from causality)
    tc_gemm<2, 0><<<dim3(Dn / BN, Sn / BM, Bn), blk>>>(
        Pp, Vp, nullptr, out, Sn, Sn, Dn, Dn,
        (long)Sn * Sn, (long)Sn * Dn, (long)Sn * Dn);
}